// round 14
// baseline (speedup 1.0000x reference)
#include <cuda_runtime.h>
#include <cuda_fp16.h>
#include <stdint.h>

#define DIMC 768
#define NH 12
#define HD 64
#define BB 16
#define NN 640
#define MROWS (BB * NN)      /* 10240 */
#define QKVN (3 * DIMC)      /* 2304 */
/* K plane pre-scaled by 0.125*log2(e); relu^2 branch rescaled by ln2^2 */
#define KSC 0.18033688011112042f
#define LN2SQ 0.4804530139182014f

/* GEMM tiling: fp16, BM=128, BN=128, BK=64, both tiles swizzled 128B rows */
#define BM 128
#define BN 128
#define BK 64
#define GST 32768            /* stage: A 16384 + B 16384 */
#define GSM_TOTAL (3 * GST)  /* 98304 */

/* scratch (allocation-free rule: __device__ globals) */
#define PLANE ((size_t)BB * NH * NN * HD)
__device__ __half g_qh[PLANE];
__device__ __half g_kh[PLANE];
__device__ __half g_vh[PLANE];
__device__ __half g_atth[(size_t)MROWS * DIMC];
__device__ __half g_xh[(size_t)MROWS * DIMC];
__device__ __half g_w1h[(size_t)QKVN * DIMC];
__device__ __half g_w2h[(size_t)DIMC * DIMC];

/* ---------------- helpers ---------------- */
__device__ __forceinline__ uint32_t smem_u32(const void* p) {
    uint32_t a;
    asm("{ .reg .u64 t; cvta.to.shared.u64 t, %1; cvt.u32.u64 %0, t; }"
        : "=r"(a) : "l"(p));
    return a;
}

__device__ __forceinline__ float ex2(float x) {
    float r;
    asm("ex2.approx.ftz.f32 %0, %1;" : "=f"(r) : "f"(x));
    return r;
}

__device__ __forceinline__ uint32_t h2pack(float a, float b) {
    __half2 h = __float22half2_rn(make_float2(a, b));
    return *reinterpret_cast<uint32_t*>(&h);
}

#define LDMATRIX_X4(r0, r1, r2, r3, addr) \
    asm volatile("ldmatrix.sync.aligned.m8n8.x4.shared.b16 {%0,%1,%2,%3}, [%4];" \
        : "=r"(r0), "=r"(r1), "=r"(r2), "=r"(r3) : "r"(addr))

#define LDMATRIX_X4_T(r0, r1, r2, r3, addr) \
    asm volatile("ldmatrix.sync.aligned.m8n8.x4.trans.shared.b16 {%0,%1,%2,%3}, [%4];" \
        : "=r"(r0), "=r"(r1), "=r"(r2), "=r"(r3) : "r"(addr))

#define MMA_F16(C, A0, A1, A2, A3, B0, B1) \
    asm volatile("mma.sync.aligned.m16n8k16.row.col.f32.f16.f16.f32 " \
        "{%0,%1,%2,%3}, {%4,%5,%6,%7}, {%8,%9}, {%0,%1,%2,%3};" \
        : "+f"((C)[0]), "+f"((C)[1]), "+f"((C)[2]), "+f"((C)[3]) \
        : "r"(A0), "r"(A1), "r"(A2), "r"(A3), "r"(B0), "r"(B1))

#define CP_ASYNC16(dst, src) \
    asm volatile("cp.async.cg.shared.global [%0], [%1], 16;" :: "r"(dst), "l"(src))
#define CP_COMMIT() asm volatile("cp.async.commit_group;" ::: "memory")
#define CP_WAIT1() asm volatile("cp.async.wait_group 1;" ::: "memory")
#define CP_WAIT0() asm volatile("cp.async.wait_group 0;" ::: "memory")

/* ------------------------------------------------------------------ */
/* prep kernels                                                        */
/* ------------------------------------------------------------------ */
__global__ void cvt_x(const float* __restrict__ x)
{
    size_t idx = (size_t)blockIdx.x * 256 + threadIdx.x;
    float4 v = ((const float4*)x)[idx];
    __half2* dst = (__half2*)g_xh;
    dst[2 * idx]     = __float22half2_rn(make_float2(v.x, v.y));
    dst[2 * idx + 1] = __float22half2_rn(make_float2(v.z, v.w));
}

__global__ void transpose_w(const float* __restrict__ in, int R, int C, int which)
{
    __shared__ float t[32][33];
    __half* out = which ? g_w2h : g_w1h;
    const int c0 = blockIdx.x * 32, r0 = blockIdx.y * 32;
    const int tx = threadIdx.x, ty = threadIdx.y;
#pragma unroll
    for (int i = 0; i < 32; i += 8)
        t[ty + i][tx] = in[(size_t)(r0 + ty + i) * C + c0 + tx];
    __syncthreads();
#pragma unroll
    for (int i = 0; i < 32; i += 8)
        out[(size_t)(c0 + ty + i) * R + r0 + tx] = __float2half_rn(t[tx][ty + i]);
}

/* ------------------------------------------------------------------ */
/* fp16 mma.sync GEMM (m16n8k16, f32 acc), cp.async 3-stage pipeline.  */
/* A-fragment ldmatrix software-pipelined one group ahead so the 4     */
/* dependent MMAs of group i overlap the LDS latency of group i+1.     */
/* EPI==0: A=g_xh, B=g_w1h -> q/k/v fp16 planes (k plane pre-scaled)   */
/* EPI==1: A=g_atth, B=g_w2h -> dense f32 out                          */
/* ------------------------------------------------------------------ */
template <int EPI>
__global__ void __launch_bounds__(256, 2)
tgemm(const float* __restrict__ bias, float* __restrict__ Cout, int N, int K)
{
    extern __shared__ char smraw[];
    const __half* Ap = (EPI == 0) ? (const __half*)g_xh : (const __half*)g_atth;
    const __half* Bt = (EPI == 0) ? (const __half*)g_w1h : (const __half*)g_w2h;

    const int tid = threadIdx.x;
    const int m0 = blockIdx.y * BM, n0 = blockIdx.x * BN;
    const int lane = tid & 31, wid = tid >> 5;
    const int wm = (wid >> 2) * 64;
    const int wn = (wid & 3) * 32;
    const int g = lane >> 2, tg = lane & 3;
    const int lr = lane & 15, half_ = lane >> 4;
    const int fr8 = lane & 7, fchi = lane >> 3;   /* b-frag ldmatrix mapping */
    const uint32_t sbase = smem_u32(smraw);

    float c[4][4][4];
#pragma unroll
    for (int mf = 0; mf < 4; mf++)
#pragma unroll
        for (int nf = 0; nf < 4; nf++)
#pragma unroll
            for (int r = 0; r < 4; r++) c[mf][nf][r] = 0.f;

#define LOAD_TILE(kt, st) do {                                                 \
    const __half* Ag = Ap + (size_t)m0 * K + (kt) * BK;                        \
    const __half* Bg = Bt + (size_t)n0 * K + (kt) * BK;                        \
    uint32_t base = sbase + (st) * GST;                                        \
    _Pragma("unroll")                                                          \
    for (int i = 0; i < 4; i++) {                                              \
        int idx = tid + i * 256;                                               \
        int row = idx >> 3, ch = idx & 7;                                      \
        uint32_t soff = row * 128 + ((ch ^ (row & 7)) * 16);                   \
        CP_ASYNC16(base + soff,         Ag + (size_t)row * K + ch * 8);        \
        CP_ASYNC16(base + 16384 + soff, Bg + (size_t)row * K + ch * 8);        \
    }                                                                          \
} while (0)

/* ldmatrix A-frag for (ks, mf) into 4-reg buffer */
#define LDMA(dst, a_s, ks, mf) do {                                            \
    int r_ = wm + (mf) * 16 + lr;                                              \
    int ch_ = (2 * (ks) + half_) ^ (r_ & 7);                                   \
    LDMATRIX_X4((dst)[0], (dst)[1], (dst)[2], (dst)[3],                        \
                (a_s) + r_ * 128 + ch_ * 16);                                  \
} while (0)

#define COMPUTE(st) do {                                                       \
    const uint32_t a_s = sbase + (st) * GST;                                   \
    const uint32_t b_s = a_s + 16384;                                          \
    _Pragma("unroll")                                                          \
    for (int kp = 0; kp < 2; kp++) {                                           \
        uint32_t b[4][4];                                                      \
        _Pragma("unroll")                                                      \
        for (int nf = 0; nf < 4; nf++) {                                       \
            int brow = wn + nf * 8 + fr8;                                      \
            int chi = 4 * kp + fchi;                                           \
            uint32_t addr = b_s + brow * 128 + ((chi ^ (brow & 7)) * 16);      \
            LDMATRIX_X4(b[nf][0], b[nf][1], b[nf][2], b[nf][3], addr);         \
        }                                                                      \
        uint32_t abuf[2][4];                                                   \
        LDMA(abuf[0], a_s, 2 * kp, 0);                                         \
        _Pragma("unroll")                                                      \
        for (int idx = 0; idx < 8; idx++) {                                    \
            const int ks2 = idx >> 2, mf = idx & 3;                            \
            if (idx + 1 < 8)                                                   \
                LDMA(abuf[(idx + 1) & 1], a_s,                                 \
                     2 * kp + ((idx + 1) >> 2), (idx + 1) & 3);                \
            const uint32_t* a = abuf[idx & 1];                                 \
            _Pragma("unroll")                                                  \
            for (int nf = 0; nf < 4; nf++)                                     \
                MMA_F16(c[mf][nf], a[0], a[1], a[2], a[3],                     \
                        b[nf][2 * ks2], b[nf][2 * ks2 + 1]);                   \
        }                                                                      \
    }                                                                          \
} while (0)

    const int nkt = K / BK;    /* 12 */
    LOAD_TILE(0, 0); CP_COMMIT();
    LOAD_TILE(1, 1); CP_COMMIT();

    for (int kt = 0; kt < nkt; kt++) {
        const int st = kt % 3;
        if (kt + 1 < nkt) CP_WAIT1(); else CP_WAIT0();
        __syncthreads();
        if (kt + 2 < nkt) {
            LOAD_TILE(kt + 2, (kt + 2) % 3);
            CP_COMMIT();
        }
        COMPUTE(st);
    }

    /* epilogue */
#pragma unroll
    for (int mf = 0; mf < 4; mf++) {
#pragma unroll
        for (int nf = 0; nf < 4; nf++) {
            const int r0 = m0 + wm + mf * 16 + g;
            const int c0 = n0 + wn + nf * 8 + 2 * tg;
            const float b0 = bias[c0], b1 = bias[c0 + 1];
            float v00 = c[mf][nf][0] + b0, v01 = c[mf][nf][1] + b1;
            float v10 = c[mf][nf][2] + b0, v11 = c[mf][nf][3] + b1;
            if (EPI == 0) {
                const int which = c0 / DIMC;
                const int rem = c0 - which * DIMC;
                const int h = rem >> 6, d = rem & 63;
                __half* pf = (which == 0) ? g_qh : (which == 1) ? g_kh : g_vh;
                const float sc = (which == 1) ? KSC : 1.f;
#pragma unroll
                for (int rr = 0; rr < 2; rr++) {
                    int m = r0 + rr * 8;
                    int bidx = m / NN, n = m - bidx * NN;
                    float vx = (rr ? v10 : v00) * sc, vy = (rr ? v11 : v01) * sc;
                    size_t off = (((size_t)(bidx * NH + h)) * NN + n) * HD + d;
                    *(__half2*)&pf[off] = __float22half2_rn(make_float2(vx, vy));
                }
            } else {
                *(float2*)&Cout[(size_t)r0 * N + c0] = make_float2(v00, v01);
                *(float2*)&Cout[(size_t)(r0 + 8) * N + c0] = make_float2(v10, v11);
            }
        }
    }
#undef LOAD_TILE
#undef LDMA
#undef COMPUTE
}

/* ------------------------------------------------------------------ */
/* Attention v8 (R12 best, unchanged): all-fp16 MMAs; row-sum via      */
/* ones-column MMA; ex2.approx with scale folded into K.               */
/* ------------------------------------------------------------------ */
#define AQ_SZ 8192
#define KVSTAGE 16384                     /* K 8192 + V 8192 */
#define ASM_TOTAL (AQ_SZ + 2 * KVSTAGE)   /* 40960 */
#define ONES_H2 0x3C003C00u               /* half2(1.0, 1.0) */

__device__ __forceinline__ void load_kv_tile(
    uint32_t stb, const __half* kh, const __half* vh, int kt, int tid)
{
#pragma unroll
    for (int i = 0; i < 4; i++) {         /* K + V: 64 rows x 8 chunks, swizzled */
        int idx = tid + i * 128;
        int row = idx >> 3, ch = idx & 7;
        uint32_t soff = row * 128 + ((ch ^ (row & 7)) * 16);
        CP_ASYNC16(stb + soff,        kh + (size_t)(kt * 64 + row) * 64 + ch * 8);
        CP_ASYNC16(stb + 8192 + soff, vh + (size_t)(kt * 64 + row) * 64 + ch * 8);
    }
}

__global__ void __launch_bounds__(128) attn8(const float* __restrict__ wblend)
{
    extern __shared__ char sm[];
    const uint32_t sb = smem_u32(sm);
    const int tid = threadIdx.x, warp = tid >> 5, lane = tid & 31;
    const int g = lane >> 2, tg = lane & 3;
    const int fr8 = lane & 7, fchi = lane >> 3;
    const int qt = blockIdx.x, h = blockIdx.y, b = blockIdx.z;

    const size_t pbase = ((size_t)(b * NH + h)) * NN * HD;
    const __half* qhp = g_qh + pbase + (size_t)qt * 64 * HD;
    const __half* khp = g_kh + pbase;
    const __half* vhp = g_vh + pbase;

    /* Q: 64 rows x 8 chunks -> swizzled 8KB */
#pragma unroll
    for (int i = 0; i < 4; i++) {
        int idx = tid + i * 128;
        int row = idx >> 3, ch = idx & 7;
        CP_ASYNC16(sb + row * 128 + ((ch ^ (row & 7)) * 16),
                   qhp + (size_t)row * 64 + ch * 8);
    }
    load_kv_tile(sb + AQ_SZ, khp, vhp, 0, tid);
    CP_COMMIT();
    CP_WAIT0();
    __syncthreads();

    /* Q A-frags in registers: 4 k16-chunks x 4 regs */
    const int qrow = warp * 16 + (lane & 15);
    const int qh16 = lane >> 4;
    uint32_t qa[4][4];
#pragma unroll
    for (int ks = 0; ks < 4; ks++) {
        uint32_t addr = sb + qrow * 128 + (((2 * ks + qh16) ^ (qrow & 7)) * 16);
        LDMATRIX_X4(qa[ks][0], qa[ks][1], qa[ks][2], qa[ks][3], addr);
    }

    float accE[8][4], accR[8][4], accL[4];
#pragma unroll
    for (int n = 0; n < 8; n++)
#pragma unroll
        for (int r = 0; r < 4; r++) { accE[n][r] = 0.f; accR[n][r] = 0.f; }
#pragma unroll
    for (int r = 0; r < 4; r++) accL[r] = 0.f;
    const float w0 = wblend[0], w1 = wblend[1];

    for (int kt = 0; kt < NN / 64; kt++) {
        const int st = kt & 1;
        if (kt + 1 < NN / 64) {
            load_kv_tile(sb + AQ_SZ + (st ^ 1) * KVSTAGE, khp, vhp, kt + 1, tid);
            CP_COMMIT();
            CP_WAIT1();
        } else {
            CP_WAIT0();
        }
        __syncthreads();

        const uint32_t kbase = sb + AQ_SZ + st * KVSTAGE;
        const uint32_t vbase = kbase + 8192;

        /* S = Q K^T : K B-frags via ldmatrix.x4 (one x4 = n8 x two k16) */
        float S[8][4];
#pragma unroll
        for (int j = 0; j < 8; j++)
#pragma unroll
            for (int r = 0; r < 4; r++) S[j][r] = 0.f;

#pragma unroll
        for (int cp = 0; cp < 2; cp++) {
#pragma unroll
            for (int j = 0; j < 8; j++) {
                int krow = j * 8 + fr8;
                int chi = 4 * cp + fchi;
                uint32_t addr = kbase + krow * 128 + ((chi ^ (krow & 7)) * 16);
                uint32_t b0, b1, b2, b3;
                LDMATRIX_X4(b0, b1, b2, b3, addr);
                const int c0 = 2 * cp, c1 = 2 * cp + 1;
                MMA_F16(S[j], qa[c0][0], qa[c0][1], qa[c0][2], qa[c0][3], b0, b1);
                MMA_F16(S[j], qa[c1][0], qa[c1][1], qa[c1][2], qa[c1][3], b2, b3);
            }
        }

        /* per 32-key half: ex2 / relu^2 -> fp16 A-frags, then PV.
           Row-sum l accumulated by MMA against a ones B-frag. */
#pragma unroll
        for (int cp = 0; cp < 2; cp++) {
            uint32_t EA[2][4], RA[2][4];
#pragma unroll
            for (int kc = 0; kc < 2; kc++) {
                const int j0 = 4 * cp + 2 * kc;
                float e[8], r[8];
#pragma unroll
                for (int t = 0; t < 4; t++) {
                    float sv = S[j0][t];
                    e[t] = ex2(sv);
                    float rm = fmaxf(sv, 0.f);
                    r[t] = rm * rm;
                }
#pragma unroll
                for (int t = 0; t < 4; t++) {
                    float sv = S[j0 + 1][t];
                    e[4 + t] = ex2(sv);
                    float rm = fmaxf(sv, 0.f);
                    r[4 + t] = rm * rm;
                }
                EA[kc][0] = h2pack(e[0], e[1]);
                EA[kc][1] = h2pack(e[2], e[3]);
                EA[kc][2] = h2pack(e[4], e[5]);
                EA[kc][3] = h2pack(e[6], e[7]);
                RA[kc][0] = h2pack(r[0], r[1]);
                RA[kc][1] = h2pack(r[2], r[3]);
                RA[kc][2] = h2pack(r[4], r[5]);
                RA[kc][3] = h2pack(r[6], r[7]);
                MMA_F16(accL, EA[kc][0], EA[kc][1], EA[kc][2], EA[kc][3],
                        ONES_H2, ONES_H2);
            }
#pragma unroll
            for (int n = 0; n < 8; n++) {
                int vrow = 32 * cp + lane;
                uint32_t addr = vbase + vrow * 128 + ((n ^ (vrow & 7)) * 16);
                uint32_t v0, v1, v2, v3;
                LDMATRIX_X4_T(v0, v1, v2, v3, addr);
                MMA_F16(accE[n], EA[0][0], EA[0][1], EA[0][2], EA[0][3], v0, v1);
                MMA_F16(accE[n], EA[1][0], EA[1][1], EA[1][2], EA[1][3], v2, v3);
                MMA_F16(accR[n], RA[0][0], RA[0][1], RA[0][2], RA[0][3], v0, v1);
                MMA_F16(accR[n], RA[1][0], RA[1][1], RA[1][2], RA[1][3], v2, v3);
            }
        }
        __syncthreads();
    }

    /* accL[0] = full row-g sum, accL[2] = full row-(g+8) sum (all lanes) */
    const float ws0 = 1.f / (1.f + __expf(w1 - w0));
    const float wr  = (1.f - ws0) * LN2SQ;      /* relu^2 branch rescale */
    const float inv0 = ws0 / accL[0];
    const float inv1 = ws0 / accL[2];

    const int row0 = b * NN + qt * 64 + warp * 16 + g;
    __half* out0 = g_atth + (size_t)row0 * DIMC + h * HD;
    __half* out1 = out0 + (size_t)8 * DIMC;
#pragma unroll
    for (int n = 0; n < 8; n++) {
        *(__half2*)(out0 + n * 8 + 2 * tg) = __float22half2_rn(make_float2(
            accE[n][0] * inv0 + accR[n][0] * wr,
            accE[n][1] * inv0 + accR[n][1] * wr));
        *(__half2*)(out1 + n * 8 + 2 * tg) = __float22half2_rn(make_float2(
            accE[n][2] * inv1 + accR[n][2] * wr,
            accE[n][3] * inv1 + accR[n][3] * wr));
    }
}

/* ------------------------------------------------------------------ */
extern "C" void kernel_launch(void* const* d_in, const int* in_sizes, int n_in,
                              void* d_out, int out_size)
{
    (void)in_sizes; (void)n_in; (void)out_size;
    const float* x      = (const float*)d_in[0];
    const float* qkv_w  = (const float*)d_in[1];
    const float* qkv_b  = (const float*)d_in[2];
    const float* proj_w = (const float*)d_in[3];
    const float* proj_b = (const float*)d_in[4];
    const float* w      = (const float*)d_in[5];
    float* out = (float*)d_out;

    cudaFuncSetAttribute(tgemm<0>, cudaFuncAttributeMaxDynamicSharedMemorySize, GSM_TOTAL);
    cudaFuncSetAttribute(tgemm<1>, cudaFuncAttributeMaxDynamicSharedMemorySize, GSM_TOTAL);
    cudaFuncSetAttribute(attn8, cudaFuncAttributeMaxDynamicSharedMemorySize, ASM_TOTAL);

    cvt_x<<<MROWS * DIMC / 1024, 256>>>(x);
    transpose_w<<<dim3(QKVN / 32, DIMC / 32), dim3(32, 8)>>>(qkv_w, DIMC, QKVN, 0);
    transpose_w<<<dim3(DIMC / 32, DIMC / 32), dim3(32, 8)>>>(proj_w, DIMC, DIMC, 1);

    dim3 g1(QKVN / BN, MROWS / BM);   /* 18 x 80 */
    tgemm<0><<<g1, 256, GSM_TOTAL>>>(qkv_b, nullptr, QKVN, DIMC);

    dim3 ga(NN / 64, NH, BB);         /* 10 x 12 x 16 */
    attn8<<<ga, 128, ASM_TOTAL>>>(w);

    dim3 g2(DIMC / BN, MROWS / BM);   /* 6 x 80 */
    tgemm<1><<<g2, 256, GSM_TOTAL>>>(proj_b, out, DIMC, DIMC);
}

// round 15
// speedup vs baseline: 1.5174x; 1.5174x over previous
#include <cuda_runtime.h>
#include <cuda_fp16.h>
#include <stdint.h>

#define DIMC 768
#define NH 12
#define HD 64
#define BB 16
#define NN 640
#define MROWS (BB * NN)      /* 10240 */
#define QKVN (3 * DIMC)      /* 2304 */
/* K plane pre-scaled by 0.125*log2(e); relu^2 branch rescaled by ln2^2 */
#define KSC 0.18033688011112042f
#define LN2SQ 0.4804530139182014f

/* GEMM tiling: fp16, BM=128, BN=128, BK=64, both tiles swizzled 128B rows */
#define BM 128
#define BN 128
#define BK 64
#define GST 32768            /* stage: A 16384 + B 16384 */
#define GSM_TOTAL (3 * GST)  /* 98304 */

/* scratch (allocation-free rule: __device__ globals) */
#define PLANE ((size_t)BB * NH * NN * HD)
__device__ __half g_qh[PLANE];
__device__ __half g_kh[PLANE];
__device__ __half g_vh[PLANE];
__device__ __half g_atth[(size_t)MROWS * DIMC];
__device__ __half g_xh[(size_t)MROWS * DIMC];
__device__ __half g_w1h[(size_t)QKVN * DIMC];
__device__ __half g_w2h[(size_t)DIMC * DIMC];

/* ---------------- helpers ---------------- */
__device__ __forceinline__ uint32_t smem_u32(const void* p) {
    uint32_t a;
    asm("{ .reg .u64 t; cvta.to.shared.u64 t, %1; cvt.u32.u64 %0, t; }"
        : "=r"(a) : "l"(p));
    return a;
}

__device__ __forceinline__ float ex2(float x) {
    float r;
    asm("ex2.approx.ftz.f32 %0, %1;" : "=f"(r) : "f"(x));
    return r;
}

__device__ __forceinline__ uint32_t h2pack(float a, float b) {
    __half2 h = __float22half2_rn(make_float2(a, b));
    return *reinterpret_cast<uint32_t*>(&h);
}

#define LDMATRIX_X4(r0, r1, r2, r3, addr) \
    asm volatile("ldmatrix.sync.aligned.m8n8.x4.shared.b16 {%0,%1,%2,%3}, [%4];" \
        : "=r"(r0), "=r"(r1), "=r"(r2), "=r"(r3) : "r"(addr))

#define LDMATRIX_X4_T(r0, r1, r2, r3, addr) \
    asm volatile("ldmatrix.sync.aligned.m8n8.x4.trans.shared.b16 {%0,%1,%2,%3}, [%4];" \
        : "=r"(r0), "=r"(r1), "=r"(r2), "=r"(r3) : "r"(addr))

#define MMA_F16(C, A0, A1, A2, A3, B0, B1) \
    asm volatile("mma.sync.aligned.m16n8k16.row.col.f32.f16.f16.f32 " \
        "{%0,%1,%2,%3}, {%4,%5,%6,%7}, {%8,%9}, {%0,%1,%2,%3};" \
        : "+f"((C)[0]), "+f"((C)[1]), "+f"((C)[2]), "+f"((C)[3]) \
        : "r"(A0), "r"(A1), "r"(A2), "r"(A3), "r"(B0), "r"(B1))

#define CP_ASYNC16(dst, src) \
    asm volatile("cp.async.cg.shared.global [%0], [%1], 16;" :: "r"(dst), "l"(src))
#define CP_COMMIT() asm volatile("cp.async.commit_group;" ::: "memory")
#define CP_WAIT2() asm volatile("cp.async.wait_group 2;" ::: "memory")
#define CP_WAIT1() asm volatile("cp.async.wait_group 1;" ::: "memory")
#define CP_WAIT0() asm volatile("cp.async.wait_group 0;" ::: "memory")

/* ------------------------------------------------------------------ */
/* prep kernels                                                        */
/* ------------------------------------------------------------------ */
__global__ void cvt_x(const float* __restrict__ x)
{
    size_t idx = (size_t)blockIdx.x * 256 + threadIdx.x;
    float4 v = ((const float4*)x)[idx];
    __half2* dst = (__half2*)g_xh;
    dst[2 * idx]     = __float22half2_rn(make_float2(v.x, v.y));
    dst[2 * idx + 1] = __float22half2_rn(make_float2(v.z, v.w));
}

/* fused transpose of both weight matrices (R=768 rows each).
   blockIdx.x < QKVN/32  -> qkv_w (C=2304) -> g_w1h
   else                  -> proj_w (C=768) -> g_w2h                   */
__global__ void transpose_w2(const float* __restrict__ w1,
                             const float* __restrict__ w2)
{
    __shared__ float t[32][33];
    const int R = DIMC;
    const bool second = (blockIdx.x >= QKVN / 32);
    const float* in = second ? w2 : w1;
    __half* out = second ? g_w2h : g_w1h;
    const int C = second ? DIMC : QKVN;
    const int c0 = (second ? (blockIdx.x - QKVN / 32) : blockIdx.x) * 32;
    const int r0 = blockIdx.y * 32;
    const int tx = threadIdx.x, ty = threadIdx.y;
#pragma unroll
    for (int i = 0; i < 32; i += 8)
        t[ty + i][tx] = in[(size_t)(r0 + ty + i) * C + c0 + tx];
    __syncthreads();
#pragma unroll
    for (int i = 0; i < 32; i += 8)
        out[(size_t)(c0 + ty + i) * R + r0 + tx] = __float2half_rn(t[tx][ty + i]);
}

/* ------------------------------------------------------------------ */
/* fp16 mma.sync GEMM (m16n8k16, f32 acc), cp.async 3-stage pipeline.  */
/* (exact R12 configuration - best measured)                           */
/* EPI==0: A=g_xh, B=g_w1h -> q/k/v fp16 planes (k plane pre-scaled)   */
/* EPI==1: A=g_atth, B=g_w2h -> dense f32 out                          */
/* ------------------------------------------------------------------ */
template <int EPI>
__global__ void __launch_bounds__(256, 2)
tgemm(const float* __restrict__ bias, float* __restrict__ Cout, int N, int K)
{
    extern __shared__ char smraw[];
    const __half* Ap = (EPI == 0) ? (const __half*)g_xh : (const __half*)g_atth;
    const __half* Bt = (EPI == 0) ? (const __half*)g_w1h : (const __half*)g_w2h;

    const int tid = threadIdx.x;
    const int m0 = blockIdx.y * BM, n0 = blockIdx.x * BN;
    const int lane = tid & 31, wid = tid >> 5;
    const int wm = (wid >> 2) * 64;
    const int wn = (wid & 3) * 32;
    const int g = lane >> 2, tg = lane & 3;
    const int lr = lane & 15, half_ = lane >> 4;
    const int fr8 = lane & 7, fchi = lane >> 3;   /* b-frag ldmatrix mapping */
    const uint32_t sbase = smem_u32(smraw);

    float c[4][4][4];
#pragma unroll
    for (int mf = 0; mf < 4; mf++)
#pragma unroll
        for (int nf = 0; nf < 4; nf++)
#pragma unroll
            for (int r = 0; r < 4; r++) c[mf][nf][r] = 0.f;

#define LOAD_TILE(kt, st) do {                                                 \
    const __half* Ag = Ap + (size_t)m0 * K + (kt) * BK;                        \
    const __half* Bg = Bt + (size_t)n0 * K + (kt) * BK;                        \
    uint32_t base = sbase + (st) * GST;                                        \
    _Pragma("unroll")                                                          \
    for (int i = 0; i < 4; i++) {                                              \
        int idx = tid + i * 256;                                               \
        int row = idx >> 3, ch = idx & 7;                                      \
        uint32_t soff = row * 128 + ((ch ^ (row & 7)) * 16);                   \
        CP_ASYNC16(base + soff,         Ag + (size_t)row * K + ch * 8);        \
        CP_ASYNC16(base + 16384 + soff, Bg + (size_t)row * K + ch * 8);        \
    }                                                                          \
} while (0)

#define COMPUTE(st) do {                                                       \
    const uint32_t a_s = sbase + (st) * GST;                                   \
    const uint32_t b_s = a_s + 16384;                                          \
    _Pragma("unroll")                                                          \
    for (int kp = 0; kp < 2; kp++) {                                           \
        uint32_t b[4][4];                                                      \
        _Pragma("unroll")                                                      \
        for (int nf = 0; nf < 4; nf++) {                                       \
            int brow = wn + nf * 8 + fr8;                                      \
            int chi = 4 * kp + fchi;                                           \
            uint32_t addr = b_s + brow * 128 + ((chi ^ (brow & 7)) * 16);      \
            LDMATRIX_X4(b[nf][0], b[nf][1], b[nf][2], b[nf][3], addr);         \
        }                                                                      \
        _Pragma("unroll")                                                      \
        for (int ks2 = 0; ks2 < 2; ks2++) {                                    \
            const int ks = 2 * kp + ks2;                                       \
            _Pragma("unroll")                                                  \
            for (int mf = 0; mf < 4; mf++) {                                   \
                uint32_t a[4];                                                 \
                int r = wm + mf * 16 + lr;                                     \
                int chunk = (2 * ks + half_) ^ (r & 7);                        \
                uint32_t addr = a_s + r * 128 + chunk * 16;                    \
                LDMATRIX_X4(a[0], a[1], a[2], a[3], addr);                     \
                _Pragma("unroll")                                              \
                for (int nf = 0; nf < 4; nf++)                                 \
                    MMA_F16(c[mf][nf], a[0], a[1], a[2], a[3],                 \
                            b[nf][2 * ks2], b[nf][2 * ks2 + 1]);               \
            }                                                                  \
        }                                                                      \
    }                                                                          \
} while (0)

    const int nkt = K / BK;    /* 12 */
    LOAD_TILE(0, 0); CP_COMMIT();
    LOAD_TILE(1, 1); CP_COMMIT();

    for (int kt = 0; kt < nkt; kt++) {
        const int st = kt % 3;
        if (kt + 1 < nkt) CP_WAIT1(); else CP_WAIT0();
        __syncthreads();
        if (kt + 2 < nkt) {
            LOAD_TILE(kt + 2, (kt + 2) % 3);
            CP_COMMIT();
        }
        COMPUTE(st);
    }

    /* epilogue */
#pragma unroll
    for (int mf = 0; mf < 4; mf++) {
#pragma unroll
        for (int nf = 0; nf < 4; nf++) {
            const int r0 = m0 + wm + mf * 16 + g;
            const int c0 = n0 + wn + nf * 8 + 2 * tg;
            const float b0 = bias[c0], b1 = bias[c0 + 1];
            float v00 = c[mf][nf][0] + b0, v01 = c[mf][nf][1] + b1;
            float v10 = c[mf][nf][2] + b0, v11 = c[mf][nf][3] + b1;
            if (EPI == 0) {
                const int which = c0 / DIMC;
                const int rem = c0 - which * DIMC;
                const int h = rem >> 6, d = rem & 63;
                __half* pf = (which == 0) ? g_qh : (which == 1) ? g_kh : g_vh;
                const float sc = (which == 1) ? KSC : 1.f;
#pragma unroll
                for (int rr = 0; rr < 2; rr++) {
                    int m = r0 + rr * 8;
                    int bidx = m / NN, n = m - bidx * NN;
                    float vx = (rr ? v10 : v00) * sc, vy = (rr ? v11 : v01) * sc;
                    size_t off = (((size_t)(bidx * NH + h)) * NN + n) * HD + d;
                    *(__half2*)&pf[off] = __float22half2_rn(make_float2(vx, vy));
                }
            } else {
                *(float2*)&Cout[(size_t)r0 * N + c0] = make_float2(v00, v01);
                *(float2*)&Cout[(size_t)(r0 + 8) * N + c0] = make_float2(v10, v11);
            }
        }
    }
#undef LOAD_TILE
#undef COMPUTE
}

/* ------------------------------------------------------------------ */
/* Attention v9: R12 numerics exactly; KV pipeline deepened to 3       */
/* stages. Row-sum via ones-column MMA; ex2.approx, scale in K plane.  */
/* CTA = 128 thr / 4 warps, 64 q-rows, 16 per warp.                    */
/* smem: Q 8KB + 3 stages x (K 8KB + V 8KB) = 57344 B.                 */
/* ------------------------------------------------------------------ */
#define AQ_SZ 8192
#define KVSTAGE 16384                     /* K 8192 + V 8192 */
#define ASM_TOTAL (AQ_SZ + 3 * KVSTAGE)   /* 57344 */
#define ONES_H2 0x3C003C00u               /* half2(1.0, 1.0) */

__device__ __forceinline__ void load_kv_tile(
    uint32_t stb, const __half* kh, const __half* vh, int kt, int tid)
{
#pragma unroll
    for (int i = 0; i < 4; i++) {         /* K + V: 64 rows x 8 chunks, swizzled */
        int idx = tid + i * 128;
        int row = idx >> 3, ch = idx & 7;
        uint32_t soff = row * 128 + ((ch ^ (row & 7)) * 16);
        CP_ASYNC16(stb + soff,        kh + (size_t)(kt * 64 + row) * 64 + ch * 8);
        CP_ASYNC16(stb + 8192 + soff, vh + (size_t)(kt * 64 + row) * 64 + ch * 8);
    }
}

__global__ void __launch_bounds__(128) attn9(const float* __restrict__ wblend)
{
    extern __shared__ char sm[];
    const uint32_t sb = smem_u32(sm);
    const int tid = threadIdx.x, warp = tid >> 5, lane = tid & 31;
    const int g = lane >> 2, tg = lane & 3;
    const int fr8 = lane & 7, fchi = lane >> 3;
    const int qt = blockIdx.x, h = blockIdx.y, b = blockIdx.z;

    const size_t pbase = ((size_t)(b * NH + h)) * NN * HD;
    const __half* qhp = g_qh + pbase + (size_t)qt * 64 * HD;
    const __half* khp = g_kh + pbase;
    const __half* vhp = g_vh + pbase;

    const int NT = NN / 64;   /* 10 */

    /* Q: 64 rows x 8 chunks -> swizzled 8KB (own commit group) */
#pragma unroll
    for (int i = 0; i < 4; i++) {
        int idx = tid + i * 128;
        int row = idx >> 3, ch = idx & 7;
        CP_ASYNC16(sb + row * 128 + ((ch ^ (row & 7)) * 16),
                   qhp + (size_t)row * 64 + ch * 8);
    }
    CP_COMMIT();
    load_kv_tile(sb + AQ_SZ, khp, vhp, 0, tid);
    CP_COMMIT();
    load_kv_tile(sb + AQ_SZ + KVSTAGE, khp, vhp, 1, tid);
    CP_COMMIT();

    /* wait for Q only (<=2 groups outstanding), consume into regs */
    CP_WAIT2();
    __syncthreads();

    const int qrow = warp * 16 + (lane & 15);
    const int qh16 = lane >> 4;
    uint32_t qa[4][4];
#pragma unroll
    for (int ks = 0; ks < 4; ks++) {
        uint32_t addr = sb + qrow * 128 + (((2 * ks + qh16) ^ (qrow & 7)) * 16);
        LDMATRIX_X4(qa[ks][0], qa[ks][1], qa[ks][2], qa[ks][3], addr);
    }

    float accE[8][4], accR[8][4], accL[4];
#pragma unroll
    for (int n = 0; n < 8; n++)
#pragma unroll
        for (int r = 0; r < 4; r++) { accE[n][r] = 0.f; accR[n][r] = 0.f; }
#pragma unroll
    for (int r = 0; r < 4; r++) accL[r] = 0.f;
    const float w0 = wblend[0], w1 = wblend[1];

    for (int kt = 0; kt < NT; kt++) {
        const int st = kt % 3;
        if (kt + 1 < NT) CP_WAIT1(); else CP_WAIT0();
        __syncthreads();
        if (kt + 2 < NT) {
            load_kv_tile(sb + AQ_SZ + ((kt + 2) % 3) * KVSTAGE, khp, vhp,
                         kt + 2, tid);
            CP_COMMIT();
        }

        const uint32_t kbase = sb + AQ_SZ + st * KVSTAGE;
        const uint32_t vbase = kbase + 8192;

        /* S = Q K^T : K B-frags via ldmatrix.x4 (one x4 = n8 x two k16) */
        float S[8][4];
#pragma unroll
        for (int j = 0; j < 8; j++)
#pragma unroll
            for (int r = 0; r < 4; r++) S[j][r] = 0.f;

#pragma unroll
        for (int cp = 0; cp < 2; cp++) {
#pragma unroll
            for (int j = 0; j < 8; j++) {
                int krow = j * 8 + fr8;
                int chi = 4 * cp + fchi;
                uint32_t addr = kbase + krow * 128 + ((chi ^ (krow & 7)) * 16);
                uint32_t b0, b1, b2, b3;
                LDMATRIX_X4(b0, b1, b2, b3, addr);
                const int c0 = 2 * cp, c1 = 2 * cp + 1;
                MMA_F16(S[j], qa[c0][0], qa[c0][1], qa[c0][2], qa[c0][3], b0, b1);
                MMA_F16(S[j], qa[c1][0], qa[c1][1], qa[c1][2], qa[c1][3], b2, b3);
            }
        }

        /* per 32-key half: ex2 / relu^2 -> fp16 A-frags, then PV.
           Row-sum l accumulated by MMA against a ones B-frag. */
#pragma unroll
        for (int cp = 0; cp < 2; cp++) {
            uint32_t EA[2][4], RA[2][4];
#pragma unroll
            for (int kc = 0; kc < 2; kc++) {
                const int j0 = 4 * cp + 2 * kc;
                float e[8], r[8];
#pragma unroll
                for (int t = 0; t < 4; t++) {
                    float sv = S[j0][t];
                    e[t] = ex2(sv);
                    float rm = fmaxf(sv, 0.f);
                    r[t] = rm * rm;
                }
#pragma unroll
                for (int t = 0; t < 4; t++) {
                    float sv = S[j0 + 1][t];
                    e[4 + t] = ex2(sv);
                    float rm = fmaxf(sv, 0.f);
                    r[4 + t] = rm * rm;
                }
                EA[kc][0] = h2pack(e[0], e[1]);
                EA[kc][1] = h2pack(e[2], e[3]);
                EA[kc][2] = h2pack(e[4], e[5]);
                EA[kc][3] = h2pack(e[6], e[7]);
                RA[kc][0] = h2pack(r[0], r[1]);
                RA[kc][1] = h2pack(r[2], r[3]);
                RA[kc][2] = h2pack(r[4], r[5]);
                RA[kc][3] = h2pack(r[6], r[7]);
                MMA_F16(accL, EA[kc][0], EA[kc][1], EA[kc][2], EA[kc][3],
                        ONES_H2, ONES_H2);
            }
#pragma unroll
            for (int n = 0; n < 8; n++) {
                int vrow = 32 * cp + lane;
                uint32_t addr = vbase + vrow * 128 + ((n ^ (vrow & 7)) * 16);
                uint32_t v0, v1, v2, v3;
                LDMATRIX_X4_T(v0, v1, v2, v3, addr);
                MMA_F16(accE[n], EA[0][0], EA[0][1], EA[0][2], EA[0][3], v0, v1);
                MMA_F16(accE[n], EA[1][0], EA[1][1], EA[1][2], EA[1][3], v2, v3);
                MMA_F16(accR[n], RA[0][0], RA[0][1], RA[0][2], RA[0][3], v0, v1);
                MMA_F16(accR[n], RA[1][0], RA[1][1], RA[1][2], RA[1][3], v2, v3);
            }
        }
        __syncthreads();
    }

    /* accL[0] = full row-g sum, accL[2] = full row-(g+8) sum (all lanes) */
    const float ws0 = 1.f / (1.f + __expf(w1 - w0));
    const float wr  = (1.f - ws0) * LN2SQ;      /* relu^2 branch rescale */
    const float inv0 = ws0 / accL[0];
    const float inv1 = ws0 / accL[2];

    const int row0 = b * NN + qt * 64 + warp * 16 + g;
    __half* out0 = g_atth + (size_t)row0 * DIMC + h * HD;
    __half* out1 = out0 + (size_t)8 * DIMC;
#pragma unroll
    for (int n = 0; n < 8; n++) {
        *(__half2*)(out0 + n * 8 + 2 * tg) = __float22half2_rn(make_float2(
            accE[n][0] * inv0 + accR[n][0] * wr,
            accE[n][1] * inv0 + accR[n][1] * wr));
        *(__half2*)(out1 + n * 8 + 2 * tg) = __float22half2_rn(make_float2(
            accE[n][2] * inv1 + accR[n][2] * wr,
            accE[n][3] * inv1 + accR[n][3] * wr));
    }
}

/* ------------------------------------------------------------------ */
extern "C" void kernel_launch(void* const* d_in, const int* in_sizes, int n_in,
                              void* d_out, int out_size)
{
    (void)in_sizes; (void)n_in; (void)out_size;
    const float* x      = (const float*)d_in[0];
    const float* qkv_w  = (const float*)d_in[1];
    const float* qkv_b  = (const float*)d_in[2];
    const float* proj_w = (const float*)d_in[3];
    const float* proj_b = (const float*)d_in[4];
    const float* w      = (const float*)d_in[5];
    float* out = (float*)d_out;

    cudaFuncSetAttribute(tgemm<0>, cudaFuncAttributeMaxDynamicSharedMemorySize, GSM_TOTAL);
    cudaFuncSetAttribute(tgemm<1>, cudaFuncAttributeMaxDynamicSharedMemorySize, GSM_TOTAL);
    cudaFuncSetAttribute(attn9, cudaFuncAttributeMaxDynamicSharedMemorySize, ASM_TOTAL);

    cvt_x<<<MROWS * DIMC / 1024, 256>>>(x);
    transpose_w2<<<dim3((QKVN + DIMC) / 32, DIMC / 32), dim3(32, 8)>>>(qkv_w, proj_w);

    dim3 g1(QKVN / BN, MROWS / BM);   /* 18 x 80 */
    tgemm<0><<<g1, 256, GSM_TOTAL>>>(qkv_b, nullptr, QKVN, DIMC);

    dim3 ga(NN / 64, NH, BB);         /* 10 x 12 x 16 */
    attn9<<<ga, 128, ASM_TOTAL>>>(w);

    dim3 g2(DIMC / BN, MROWS / BM);   /* 6 x 80 */
    tgemm<1><<<g2, 256, GSM_TOTAL>>>(proj_b, out, DIMC, DIMC);
}

// round 16
// speedup vs baseline: 1.5582x; 1.0269x over previous
#include <cuda_runtime.h>
#include <cuda_fp16.h>
#include <stdint.h>

#define DIMC 768
#define NH 12
#define HD 64
#define BB 16
#define NN 640
#define MROWS (BB * NN)      /* 10240 */
#define QKVN (3 * DIMC)      /* 2304 */
/* K plane pre-scaled by 0.125*log2(e); relu^2 branch rescaled by ln2^2 */
#define KSC 0.18033688011112042f
#define LN2SQ 0.4804530139182014f

/* GEMM tiling: fp16, BM=128, BN=128, BK=64, both tiles swizzled 128B rows */
#define BM 128
#define BN 128
#define BK 64
#define GST 32768            /* stage: A 16384 + B 16384 */
#define GSM_TOTAL (3 * GST)  /* 98304 */

/* scratch (allocation-free rule: __device__ globals) */
#define PLANE ((size_t)BB * NH * NN * HD)
__device__ __half g_qh[PLANE];
__device__ __half g_kh[PLANE];
__device__ __half g_vh[PLANE];
__device__ __half g_atth[(size_t)MROWS * DIMC];
__device__ __half g_xh[(size_t)MROWS * DIMC];
__device__ __half g_w1h[(size_t)QKVN * DIMC];
__device__ __half g_w2h[(size_t)DIMC * DIMC];

/* ---------------- helpers ---------------- */
__device__ __forceinline__ uint32_t smem_u32(const void* p) {
    uint32_t a;
    asm("{ .reg .u64 t; cvta.to.shared.u64 t, %1; cvt.u32.u64 %0, t; }"
        : "=r"(a) : "l"(p));
    return a;
}

/* pack two f32 into f16x2: lo = a, hi = b */
__device__ __forceinline__ uint32_t f2h2(float a, float b) {
    uint32_t d;
    asm("cvt.rn.f16x2.f32 %0, %2, %1;" : "=r"(d) : "f"(a), "f"(b));
    return d;
}

__device__ __forceinline__ uint32_t ex2h2(uint32_t s) {
    uint32_t d;
    asm("ex2.approx.f16x2 %0, %1;" : "=r"(d) : "r"(s));
    return d;
}

__device__ __forceinline__ uint32_t relusq_h2(uint32_t s) {
    uint32_t m, d;
    asm("max.f16x2 %0, %1, %2;" : "=r"(m) : "r"(s), "r"(0u));
    asm("mul.f16x2 %0, %1, %1;" : "=r"(d) : "r"(m));
    return d;
}

#define LDMATRIX_X4(r0, r1, r2, r3, addr) \
    asm volatile("ldmatrix.sync.aligned.m8n8.x4.shared.b16 {%0,%1,%2,%3}, [%4];" \
        : "=r"(r0), "=r"(r1), "=r"(r2), "=r"(r3) : "r"(addr))

#define LDMATRIX_X4_T(r0, r1, r2, r3, addr) \
    asm volatile("ldmatrix.sync.aligned.m8n8.x4.trans.shared.b16 {%0,%1,%2,%3}, [%4];" \
        : "=r"(r0), "=r"(r1), "=r"(r2), "=r"(r3) : "r"(addr))

#define MMA_F16(C, A0, A1, A2, A3, B0, B1) \
    asm volatile("mma.sync.aligned.m16n8k16.row.col.f32.f16.f16.f32 " \
        "{%0,%1,%2,%3}, {%4,%5,%6,%7}, {%8,%9}, {%0,%1,%2,%3};" \
        : "+f"((C)[0]), "+f"((C)[1]), "+f"((C)[2]), "+f"((C)[3]) \
        : "r"(A0), "r"(A1), "r"(A2), "r"(A3), "r"(B0), "r"(B1))

#define CP_ASYNC16(dst, src) \
    asm volatile("cp.async.cg.shared.global [%0], [%1], 16;" :: "r"(dst), "l"(src))
#define CP_COMMIT() asm volatile("cp.async.commit_group;" ::: "memory")
#define CP_WAIT2() asm volatile("cp.async.wait_group 2;" ::: "memory")
#define CP_WAIT1() asm volatile("cp.async.wait_group 1;" ::: "memory")
#define CP_WAIT0() asm volatile("cp.async.wait_group 0;" ::: "memory")

/* ------------------------------------------------------------------ */
/* prep kernels                                                        */
/* ------------------------------------------------------------------ */
__global__ void cvt_x(const float* __restrict__ x)
{
    size_t idx = (size_t)blockIdx.x * 256 + threadIdx.x;
    float4 v = ((const float4*)x)[idx];
    __half2* dst = (__half2*)g_xh;
    dst[2 * idx]     = __float22half2_rn(make_float2(v.x, v.y));
    dst[2 * idx + 1] = __float22half2_rn(make_float2(v.z, v.w));
}

/* fused transpose of both weight matrices (R=768 rows each) */
__global__ void transpose_w2(const float* __restrict__ w1,
                             const float* __restrict__ w2)
{
    __shared__ float t[32][33];
    const int R = DIMC;
    const bool second = (blockIdx.x >= QKVN / 32);
    const float* in = second ? w2 : w1;
    __half* out = second ? g_w2h : g_w1h;
    const int C = second ? DIMC : QKVN;
    const int c0 = (second ? (blockIdx.x - QKVN / 32) : blockIdx.x) * 32;
    const int r0 = blockIdx.y * 32;
    const int tx = threadIdx.x, ty = threadIdx.y;
#pragma unroll
    for (int i = 0; i < 32; i += 8)
        t[ty + i][tx] = in[(size_t)(r0 + ty + i) * C + c0 + tx];
    __syncthreads();
#pragma unroll
    for (int i = 0; i < 32; i += 8)
        out[(size_t)(c0 + ty + i) * R + r0 + tx] = __float2half_rn(t[tx][ty + i]);
}

/* ------------------------------------------------------------------ */
/* fp16 mma.sync GEMM (m16n8k16, f32 acc), cp.async 3-stage pipeline.  */
/* (exact R12/R15 configuration - best measured)                       */
/* ------------------------------------------------------------------ */
template <int EPI>
__global__ void __launch_bounds__(256, 2)
tgemm(const float* __restrict__ bias, float* __restrict__ Cout, int N, int K)
{
    extern __shared__ char smraw[];
    const __half* Ap = (EPI == 0) ? (const __half*)g_xh : (const __half*)g_atth;
    const __half* Bt = (EPI == 0) ? (const __half*)g_w1h : (const __half*)g_w2h;

    const int tid = threadIdx.x;
    const int m0 = blockIdx.y * BM, n0 = blockIdx.x * BN;
    const int lane = tid & 31, wid = tid >> 5;
    const int wm = (wid >> 2) * 64;
    const int wn = (wid & 3) * 32;
    const int g = lane >> 2, tg = lane & 3;
    const int lr = lane & 15, half_ = lane >> 4;
    const int fr8 = lane & 7, fchi = lane >> 3;
    const uint32_t sbase = smem_u32(smraw);

    float c[4][4][4];
#pragma unroll
    for (int mf = 0; mf < 4; mf++)
#pragma unroll
        for (int nf = 0; nf < 4; nf++)
#pragma unroll
            for (int r = 0; r < 4; r++) c[mf][nf][r] = 0.f;

#define LOAD_TILE(kt, st) do {                                                 \
    const __half* Ag = Ap + (size_t)m0 * K + (kt) * BK;                        \
    const __half* Bg = Bt + (size_t)n0 * K + (kt) * BK;                        \
    uint32_t base = sbase + (st) * GST;                                        \
    _Pragma("unroll")                                                          \
    for (int i = 0; i < 4; i++) {                                              \
        int idx = tid + i * 256;                                               \
        int row = idx >> 3, ch = idx & 7;                                      \
        uint32_t soff = row * 128 + ((ch ^ (row & 7)) * 16);                   \
        CP_ASYNC16(base + soff,         Ag + (size_t)row * K + ch * 8);        \
        CP_ASYNC16(base + 16384 + soff, Bg + (size_t)row * K + ch * 8);        \
    }                                                                          \
} while (0)

#define COMPUTE(st) do {                                                       \
    const uint32_t a_s = sbase + (st) * GST;                                   \
    const uint32_t b_s = a_s + 16384;                                          \
    _Pragma("unroll")                                                          \
    for (int kp = 0; kp < 2; kp++) {                                           \
        uint32_t b[4][4];                                                      \
        _Pragma("unroll")                                                      \
        for (int nf = 0; nf < 4; nf++) {                                       \
            int brow = wn + nf * 8 + fr8;                                      \
            int chi = 4 * kp + fchi;                                           \
            uint32_t addr = b_s + brow * 128 + ((chi ^ (brow & 7)) * 16);      \
            LDMATRIX_X4(b[nf][0], b[nf][1], b[nf][2], b[nf][3], addr);         \
        }                                                                      \
        _Pragma("unroll")                                                      \
        for (int ks2 = 0; ks2 < 2; ks2++) {                                    \
            const int ks = 2 * kp + ks2;                                       \
            _Pragma("unroll")                                                  \
            for (int mf = 0; mf < 4; mf++) {                                   \
                uint32_t a[4];                                                 \
                int r = wm + mf * 16 + lr;                                     \
                int chunk = (2 * ks + half_) ^ (r & 7);                        \
                uint32_t addr = a_s + r * 128 + chunk * 16;                    \
                LDMATRIX_X4(a[0], a[1], a[2], a[3], addr);                     \
                _Pragma("unroll")                                              \
                for (int nf = 0; nf < 4; nf++)                                 \
                    MMA_F16(c[mf][nf], a[0], a[1], a[2], a[3],                 \
                            b[nf][2 * ks2], b[nf][2 * ks2 + 1]);               \
            }                                                                  \
        }                                                                      \
    }                                                                          \
} while (0)

    const int nkt = K / BK;    /* 12 */
    LOAD_TILE(0, 0); CP_COMMIT();
    LOAD_TILE(1, 1); CP_COMMIT();

    for (int kt = 0; kt < nkt; kt++) {
        const int st = kt % 3;
        if (kt + 1 < nkt) CP_WAIT1(); else CP_WAIT0();
        __syncthreads();
        if (kt + 2 < nkt) {
            LOAD_TILE(kt + 2, (kt + 2) % 3);
            CP_COMMIT();
        }
        COMPUTE(st);
    }

    /* epilogue */
#pragma unroll
    for (int mf = 0; mf < 4; mf++) {
#pragma unroll
        for (int nf = 0; nf < 4; nf++) {
            const int r0 = m0 + wm + mf * 16 + g;
            const int c0 = n0 + wn + nf * 8 + 2 * tg;
            const float b0 = bias[c0], b1 = bias[c0 + 1];
            float v00 = c[mf][nf][0] + b0, v01 = c[mf][nf][1] + b1;
            float v10 = c[mf][nf][2] + b0, v11 = c[mf][nf][3] + b1;
            if (EPI == 0) {
                const int which = c0 / DIMC;
                const int rem = c0 - which * DIMC;
                const int h = rem >> 6, d = rem & 63;
                __half* pf = (which == 0) ? g_qh : (which == 1) ? g_kh : g_vh;
                const float sc = (which == 1) ? KSC : 1.f;
#pragma unroll
                for (int rr = 0; rr < 2; rr++) {
                    int m = r0 + rr * 8;
                    int bidx = m / NN, n = m - bidx * NN;
                    float vx = (rr ? v10 : v00) * sc, vy = (rr ? v11 : v01) * sc;
                    size_t off = (((size_t)(bidx * NH + h)) * NN + n) * HD + d;
                    *(__half2*)&pf[off] = __float22half2_rn(make_float2(vx, vy));
                }
            } else {
                *(float2*)&Cout[(size_t)r0 * N + c0] = make_float2(v00, v01);
                *(float2*)&Cout[(size_t)(r0 + 8) * N + c0] = make_float2(v10, v11);
            }
        }
    }
#undef LOAD_TILE
#undef COMPUTE
}

/* ------------------------------------------------------------------ */
/* Attention v10: R15 structure (3-stage KV pipeline, ones-column MMA  */
/* row-sum) with the S->(E,R) conversion vectorized in f16x2:          */
/*   cvt.rn.f16x2 -> ex2.approx.f16x2 (E) / max+mul.f16x2 (R).         */
/* Halves the scalar section; outputs are A-frags directly.            */
/* ------------------------------------------------------------------ */
#define AQ_SZ 8192
#define KVSTAGE 16384                     /* K 8192 + V 8192 */
#define ASM_TOTAL (AQ_SZ + 3 * KVSTAGE)   /* 57344 */
#define ONES_H2 0x3C003C00u               /* half2(1.0, 1.0) */

__device__ __forceinline__ void load_kv_tile(
    uint32_t stb, const __half* kh, const __half* vh, int kt, int tid)
{
#pragma unroll
    for (int i = 0; i < 4; i++) {         /* K + V: 64 rows x 8 chunks, swizzled */
        int idx = tid + i * 128;
        int row = idx >> 3, ch = idx & 7;
        uint32_t soff = row * 128 + ((ch ^ (row & 7)) * 16);
        CP_ASYNC16(stb + soff,        kh + (size_t)(kt * 64 + row) * 64 + ch * 8);
        CP_ASYNC16(stb + 8192 + soff, vh + (size_t)(kt * 64 + row) * 64 + ch * 8);
    }
}

__global__ void __launch_bounds__(128) attn10(const float* __restrict__ wblend)
{
    extern __shared__ char sm[];
    const uint32_t sb = smem_u32(sm);
    const int tid = threadIdx.x, warp = tid >> 5, lane = tid & 31;
    const int g = lane >> 2, tg = lane & 3;
    const int fr8 = lane & 7, fchi = lane >> 3;
    const int qt = blockIdx.x, h = blockIdx.y, b = blockIdx.z;

    const size_t pbase = ((size_t)(b * NH + h)) * NN * HD;
    const __half* qhp = g_qh + pbase + (size_t)qt * 64 * HD;
    const __half* khp = g_kh + pbase;
    const __half* vhp = g_vh + pbase;

    const int NT = NN / 64;   /* 10 */

    /* Q: 64 rows x 8 chunks -> swizzled 8KB (own commit group) */
#pragma unroll
    for (int i = 0; i < 4; i++) {
        int idx = tid + i * 128;
        int row = idx >> 3, ch = idx & 7;
        CP_ASYNC16(sb + row * 128 + ((ch ^ (row & 7)) * 16),
                   qhp + (size_t)row * 64 + ch * 8);
    }
    CP_COMMIT();
    load_kv_tile(sb + AQ_SZ, khp, vhp, 0, tid);
    CP_COMMIT();
    load_kv_tile(sb + AQ_SZ + KVSTAGE, khp, vhp, 1, tid);
    CP_COMMIT();

    CP_WAIT2();
    __syncthreads();

    const int qrow = warp * 16 + (lane & 15);
    const int qh16 = lane >> 4;
    uint32_t qa[4][4];
#pragma unroll
    for (int ks = 0; ks < 4; ks++) {
        uint32_t addr = sb + qrow * 128 + (((2 * ks + qh16) ^ (qrow & 7)) * 16);
        LDMATRIX_X4(qa[ks][0], qa[ks][1], qa[ks][2], qa[ks][3], addr);
    }

    float accE[8][4], accR[8][4], accL[4];
#pragma unroll
    for (int n = 0; n < 8; n++)
#pragma unroll
        for (int r = 0; r < 4; r++) { accE[n][r] = 0.f; accR[n][r] = 0.f; }
#pragma unroll
    for (int r = 0; r < 4; r++) accL[r] = 0.f;
    const float w0 = wblend[0], w1 = wblend[1];

    for (int kt = 0; kt < NT; kt++) {
        const int st = kt % 3;
        if (kt + 1 < NT) CP_WAIT1(); else CP_WAIT0();
        __syncthreads();
        if (kt + 2 < NT) {
            load_kv_tile(sb + AQ_SZ + ((kt + 2) % 3) * KVSTAGE, khp, vhp,
                         kt + 2, tid);
            CP_COMMIT();
        }

        const uint32_t kbase = sb + AQ_SZ + st * KVSTAGE;
        const uint32_t vbase = kbase + 8192;

        /* S = Q K^T */
        float S[8][4];
#pragma unroll
        for (int j = 0; j < 8; j++)
#pragma unroll
            for (int r = 0; r < 4; r++) S[j][r] = 0.f;

#pragma unroll
        for (int cp = 0; cp < 2; cp++) {
#pragma unroll
            for (int j = 0; j < 8; j++) {
                int krow = j * 8 + fr8;
                int chi = 4 * cp + fchi;
                uint32_t addr = kbase + krow * 128 + ((chi ^ (krow & 7)) * 16);
                uint32_t b0, b1, b2, b3;
                LDMATRIX_X4(b0, b1, b2, b3, addr);
                const int c0 = 2 * cp, c1 = 2 * cp + 1;
                MMA_F16(S[j], qa[c0][0], qa[c0][1], qa[c0][2], qa[c0][3], b0, b1);
                MMA_F16(S[j], qa[c1][0], qa[c1][1], qa[c1][2], qa[c1][3], b2, b3);
            }
        }

        /* per 32-key half: f16x2 conversion -> E/R A-frags, then PV.
           Row-sum l accumulated by MMA against a ones B-frag. */
#pragma unroll
        for (int cp = 0; cp < 2; cp++) {
            uint32_t EA[2][4], RA[2][4];
#pragma unroll
            for (int kc = 0; kc < 2; kc++) {
                const int j0 = 4 * cp + 2 * kc;
                uint32_t sh[4];
                sh[0] = f2h2(S[j0][0],     S[j0][1]);
                sh[1] = f2h2(S[j0][2],     S[j0][3]);
                sh[2] = f2h2(S[j0 + 1][0], S[j0 + 1][1]);
                sh[3] = f2h2(S[j0 + 1][2], S[j0 + 1][3]);
#pragma unroll
                for (int i = 0; i < 4; i++) {
                    EA[kc][i] = ex2h2(sh[i]);
                    RA[kc][i] = relusq_h2(sh[i]);
                }
                MMA_F16(accL, EA[kc][0], EA[kc][1], EA[kc][2], EA[kc][3],
                        ONES_H2, ONES_H2);
            }
#pragma unroll
            for (int n = 0; n < 8; n++) {
                int vrow = 32 * cp + lane;
                uint32_t addr = vbase + vrow * 128 + ((n ^ (vrow & 7)) * 16);
                uint32_t v0, v1, v2, v3;
                LDMATRIX_X4_T(v0, v1, v2, v3, addr);
                MMA_F16(accE[n], EA[0][0], EA[0][1], EA[0][2], EA[0][3], v0, v1);
                MMA_F16(accE[n], EA[1][0], EA[1][1], EA[1][2], EA[1][3], v2, v3);
                MMA_F16(accR[n], RA[0][0], RA[0][1], RA[0][2], RA[0][3], v0, v1);
                MMA_F16(accR[n], RA[1][0], RA[1][1], RA[1][2], RA[1][3], v2, v3);
            }
        }
        __syncthreads();
    }

    /* accL[0] = full row-g sum, accL[2] = full row-(g+8) sum (all lanes) */
    const float ws0 = 1.f / (1.f + __expf(w1 - w0));
    const float wr  = (1.f - ws0) * LN2SQ;      /* relu^2 branch rescale */
    const float inv0 = ws0 / accL[0];
    const float inv1 = ws0 / accL[2];

    const int row0 = b * NN + qt * 64 + warp * 16 + g;
    __half* out0 = g_atth + (size_t)row0 * DIMC + h * HD;
    __half* out1 = out0 + (size_t)8 * DIMC;
#pragma unroll
    for (int n = 0; n < 8; n++) {
        *(__half2*)(out0 + n * 8 + 2 * tg) = __float22half2_rn(make_float2(
            accE[n][0] * inv0 + accR[n][0] * wr,
            accE[n][1] * inv0 + accR[n][1] * wr));
        *(__half2*)(out1 + n * 8 + 2 * tg) = __float22half2_rn(make_float2(
            accE[n][2] * inv1 + accR[n][2] * wr,
            accE[n][3] * inv1 + accR[n][3] * wr));
    }
}

/* ------------------------------------------------------------------ */
extern "C" void kernel_launch(void* const* d_in, const int* in_sizes, int n_in,
                              void* d_out, int out_size)
{
    (void)in_sizes; (void)n_in; (void)out_size;
    const float* x      = (const float*)d_in[0];
    const float* qkv_w  = (const float*)d_in[1];
    const float* qkv_b  = (const float*)d_in[2];
    const float* proj_w = (const float*)d_in[3];
    const float* proj_b = (const float*)d_in[4];
    const float* w      = (const float*)d_in[5];
    float* out = (float*)d_out;

    cudaFuncSetAttribute(tgemm<0>, cudaFuncAttributeMaxDynamicSharedMemorySize, GSM_TOTAL);
    cudaFuncSetAttribute(tgemm<1>, cudaFuncAttributeMaxDynamicSharedMemorySize, GSM_TOTAL);
    cudaFuncSetAttribute(attn10, cudaFuncAttributeMaxDynamicSharedMemorySize, ASM_TOTAL);

    cvt_x<<<MROWS * DIMC / 1024, 256>>>(x);
    transpose_w2<<<dim3((QKVN + DIMC) / 32, DIMC / 32), dim3(32, 8)>>>(qkv_w, proj_w);

    dim3 g1(QKVN / BN, MROWS / BM);   /* 18 x 80 */
    tgemm<0><<<g1, 256, GSM_TOTAL>>>(qkv_b, nullptr, QKVN, DIMC);

    dim3 ga(NN / 64, NH, BB);         /* 10 x 12 x 16 */
    attn10<<<ga, 128, ASM_TOTAL>>>(w);

    dim3 g2(DIMC / BN, MROWS / BM);   /* 6 x 80 */
    tgemm<1><<<g2, 256, GSM_TOTAL>>>(proj_b, out, DIMC, DIMC);
}